// round 17
// baseline (speedup 1.0000x reference)
#include <cuda_runtime.h>
#include <cstddef>
#include <cstdint>

// Problem constants
#define NB   16
#define NT   64
#define NF0  8
#define NN   100
#define BT   (NB * NT)            // 1024
#define ROWSTRIDE (NF0 * NN)      // 800 floats per (b,t) slice
#define SLAB ((size_t)BT * ROWSTRIDE)  // 819200 floats per k-slab

__device__ float  g_z[15 * BT * ROWSTRIDE];  // slabs k=1..15 (~49 MB)
__device__ float2 g_w2p[64 * 96];            // w2 pre-split {tf32hi, tf32lo}

// ---- packed f32x2 helpers (diffusion only) ----
typedef unsigned long long ull;
__device__ __forceinline__ ull pack2(float lo, float hi) {
    ull r; asm("mov.b64 %0, {%1,%2};" : "=l"(r) : "f"(lo), "f"(hi)); return r;
}
__device__ __forceinline__ void unpack2(ull v, float& lo, float& hi) {
    asm("mov.b64 {%0,%1}, %2;" : "=f"(lo), "=f"(hi) : "l"(v));
}
__device__ __forceinline__ ull ffma2(ull a, ull b, ull c) {
    ull d; asm("fma.rn.f32x2 %0, %1, %2, %3;" : "=l"(d) : "l"(a), "l"(b), "l"(c));
    return d;
}

// ---- tf32 helpers ----
__device__ __forceinline__ uint32_t tf32_of(float x) {
    uint32_t u; asm("cvt.rna.tf32.f32 %0, %1;" : "=r"(u) : "f"(x)); return u;
}
__device__ __forceinline__ void tf32_split(float x, uint32_t& hi, uint32_t& lo) {
    hi = tf32_of(x);
    lo = tf32_of(x - __uint_as_float(hi));
}
__device__ __forceinline__ void mma_tf32(
    float& d0, float& d1, float& d2, float& d3,
    uint32_t a0, uint32_t a1, uint32_t a2, uint32_t a3,
    uint32_t b0, uint32_t b1)
{
    asm volatile(
        "mma.sync.aligned.m16n8k8.row.col.f32.tf32.tf32.f32 "
        "{%0,%1,%2,%3}, {%4,%5,%6,%7}, {%8,%9}, {%0,%1,%2,%3};"
        : "+f"(d0), "+f"(d1), "+f"(d2), "+f"(d3)
        : "r"(a0), "r"(a1), "r"(a2), "r"(a3), "r"(b0), "r"(b1));
}
// 3-term split MMA: hi*hi + lo*hi + hi*lo (~fp32 accuracy)
__device__ __forceinline__ void mma3(
    float* c,
    uint32_t ah0, uint32_t al0, uint32_t ah1, uint32_t al1,
    uint32_t ah2, uint32_t al2, uint32_t ah3, uint32_t al3,
    uint32_t bh0, uint32_t bl0, uint32_t bh1, uint32_t bl1)
{
    mma_tf32(c[0], c[1], c[2], c[3], ah0, ah1, ah2, ah3, bh0, bh1);
    mma_tf32(c[0], c[1], c[2], c[3], al0, al1, al2, al3, bh0, bh1);
    mma_tf32(c[0], c[1], c[2], c[3], ah0, ah1, ah2, ah3, bl0, bl1);
}

// ---------------------------------------------------------------------------
// Init: pre-split w2 into global {hi,lo} pairs (L1-resident for all blocks)
// ---------------------------------------------------------------------------
__global__ void split_w2_kernel(const float* __restrict__ w2g)
{
    int i = blockIdx.x * 256 + threadIdx.x;
    if (i < 6144) {
        uint32_t hi, lo;
        tf32_split(w2g[i], hi, lo);
        g_w2p[i] = make_float2(__uint_as_float(hi), __uint_as_float(lo));
    }
}

// ---------------------------------------------------------------------------
// Diffusion step k (R9 structure; unroll 10 for deeper MLP)
// ---------------------------------------------------------------------------
__global__ __launch_bounds__(128)
void diffuse_step_kernel(const float* __restrict__ x,
                         const float* __restrict__ S,
                         int k)
{
    int bt  = blockIdx.x;
    int t   = bt & 63;
    if (t < k) return;
    int tid = threadIdx.x;

    const float* src = (k == 1)
        ? (x + (size_t)(bt - 1) * ROWSTRIDE)
        : (g_z + (size_t)(k - 2) * SLAB + (size_t)(bt - 1) * ROWSTRIDE);

    __shared__ float At[NN * NF0];            // [n][f]
    for (int i = tid; i < ROWSTRIDE; i += 128) {
        int f = i / NN, n = i % NN;
        At[n * 8 + f] = src[i];
    }
    __syncthreads();

    if (tid < 100) {
        int m = tid;
        const float* Sp = S + (size_t)bt * (NN * NN) + m;

        ull a01 = 0ull, a23 = 0ull, a45 = 0ull, a67 = 0ull;
        #pragma unroll 10
        for (int n = 0; n < NN; n++) {
            float s = Sp[(size_t)n * NN];
            ull s2 = pack2(s, s);
            const ull* ar = reinterpret_cast<const ull*>(At + n * 8);
            a01 = ffma2(ar[0], s2, a01);
            a23 = ffma2(ar[1], s2, a23);
            a45 = ffma2(ar[2], s2, a45);
            a67 = ffma2(ar[3], s2, a67);
        }
        float* dst = g_z + (size_t)(k - 1) * SLAB + (size_t)bt * ROWSTRIDE + m;
        float v0, v1;
        unpack2(a01, v0, v1); dst[0 * NN] = v0; dst[1 * NN] = v1;
        unpack2(a23, v0, v1); dst[2 * NN] = v0; dst[3 * NN] = v1;
        unpack2(a45, v0, v1); dst[4 * NN] = v0; dst[5 * NN] = v1;
        unpack2(a67, v0, v1); dst[6 * NN] = v0; dst[7 * NN] = v1;
    }
}

// ---------------------------------------------------------------------------
// Fused head, LOW-SMEM: conv/fc weights stream from L1-resident global.
// conv1/conv2/fc1 on 3xTF32 MMA; fc2 scalar. 32 rows/block, 256 threads,
// 3 blocks/SM (56.1 KB smem).
//
// Smem (floats):
//  [0,4128)       zsh (32x129) -> reused as y2sh
//  [4128,6208)    hsh (32x65)
//  [6208,12384)   y1sh (32x193)
//  [12384,13536)  w1sh fp32 [n*36+k]
//  [13536,13568)  b1   [13568,13632) b2
//  [13632,13696)  fc1b [13696,14016) fc2w [14016,14021) fc2b
// ---------------------------------------------------------------------------
#define ZS   129
#define Y1S  193
#define Y2S  129
#define HS   65
#define OFF_HSH  4128
#define OFF_Y1   6208
#define OFF_W1   12384
#define OFF_B1   13536
#define OFF_B2   13568
#define OFF_F1B  13632
#define OFF_F2W  13696
#define OFF_F2B  14016
#define SMEM_FLOATS 14021

__global__ __launch_bounds__(256, 3)
void head_kernel(const float* __restrict__ x,
                 const float* __restrict__ w1g, const float* __restrict__ b1g,
                 const float* __restrict__ w2g, const float* __restrict__ b2g,
                 const float* __restrict__ f1wg, const float* __restrict__ f1bg,
                 const float* __restrict__ f2wg, const float* __restrict__ f2bg,
                 float* __restrict__ out)
{
    extern __shared__ float sm[];
    float* zsh  = sm;
    float* y2sh = sm;                 // reuses zsh region after conv1
    float* hsh  = sm + OFF_HSH;
    float* y1sh = sm + OFF_Y1;
    float* w1sh = sm + OFF_W1;
    float* b1sh = sm + OFF_B1;
    float* b2sh = sm + OFF_B2;

    int tid  = threadIdx.x;
    int row0 = blockIdx.x * 32;       // global row = (b*T + t)*N + n
    int lane = tid & 31, wrp = tid >> 5;
    int gr = lane >> 2, tg = lane & 3;

    // ---- stage 0: gather z tile + small weights/biases ----
    for (int i = tid; i < 4096; i += 256) {
        int r  = i & 31;
        int kf = i >> 5;
        int f  = kf >> 4;
        int k  = kf & 15;
        int R  = row0 + r;
        int n  = R % NN;
        int bt = R / NN;
        float v;
        if (k == 0) {
            v = x[(size_t)bt * ROWSTRIDE + f * NN + n];
        } else if ((bt & 63) < k) {
            v = 0.f;                  // triangular zero region (never stored)
        } else {
            v = g_z[(size_t)(k - 1) * SLAB + (size_t)bt * ROWSTRIDE + f * NN + n];
        }
        zsh[r * ZS + f * 16 + k] = v;
    }
    for (int i = tid; i < 1024; i += 256) {
        int n = i >> 5, k = i & 31;
        w1sh[n * 36 + k] = w1g[i];    // padded stride 36
    }
    if (tid < 32)  b1sh[tid] = b1g[tid];
    if (tid < 64)  b2sh[tid] = b2g[tid];
    if (tid < 64)  sm[OFF_F1B + tid] = f1bg[tid];
    for (int i = tid; i < 320; i += 256) sm[OFF_F2W + i] = f2wg[i];
    if (tid < 5)   sm[OFF_F2B + tid] = f2bg[tid];
    __syncthreads();

    // ---- conv1 via 3xTF32 MMA + relu + pool2 (weights from smem) ----
    {
        #pragma unroll
        for (int i3 = 0; i3 < 3; i3++) {
            int mt = wrp + 8 * i3;
            int rowLo = 16 * mt + gr;
            int rowHi = rowLo + 8;
            int rLo = rowLo / 12, pLo = rowLo % 12;
            int rHi = rowHi / 12, pHi = rowHi % 12;

            float acc[4][4];
            #pragma unroll
            for (int nt = 0; nt < 4; nt++)
                #pragma unroll
                for (int s = 0; s < 4; s++) acc[nt][s] = 0.f;

            #pragma unroll
            for (int ks = 0; ks < 4; ks++) {
                float a0f = zsh[rLo * ZS + (2 * ks) * 16 + tg + pLo];
                float a1f = zsh[rHi * ZS + (2 * ks) * 16 + tg + pHi];
                float a2f = zsh[rLo * ZS + (2 * ks + 1) * 16 + tg + pLo];
                float a3f = zsh[rHi * ZS + (2 * ks + 1) * 16 + tg + pHi];
                uint32_t ah0, al0, ah1, al1, ah2, al2, ah3, al3;
                tf32_split(a0f, ah0, al0);
                tf32_split(a1f, ah1, al1);
                tf32_split(a2f, ah2, al2);
                tf32_split(a3f, ah3, al3);

                #pragma unroll
                for (int nt = 0; nt < 4; nt++) {
                    int n = nt * 8 + gr;
                    float b0f = w1sh[n * 36 + 8 * ks + tg];
                    float b1f = w1sh[n * 36 + 8 * ks + tg + 4];
                    uint32_t bh0, bl0, bh1, bl1;
                    tf32_split(b0f, bh0, bl0);
                    tf32_split(b1f, bh1, bl1);
                    mma3(acc[nt], ah0, al0, ah1, al1, ah2, al2, ah3, al3,
                         bh0, bl0, bh1, bl1);
                }
            }
            #pragma unroll
            for (int nt = 0; nt < 4; nt++) {
                int f1a = nt * 8 + 2 * tg;
                float ba = b1sh[f1a], bb = b1sh[f1a + 1];
                float v0 = fmaxf(acc[nt][0] + ba, 0.f);
                float v1 = fmaxf(acc[nt][1] + bb, 0.f);
                float v2 = fmaxf(acc[nt][2] + ba, 0.f);
                float v3 = fmaxf(acc[nt][3] + bb, 0.f);
                float p0 = __shfl_xor_sync(0xffffffffu, v0, 4);
                float p1 = __shfl_xor_sync(0xffffffffu, v1, 4);
                float p2 = __shfl_xor_sync(0xffffffffu, v2, 4);
                float p3 = __shfl_xor_sync(0xffffffffu, v3, 4);
                if ((gr & 1) == 0) {
                    int lpLo = pLo >> 1;
                    int lpHi = pHi >> 1;
                    y1sh[rLo * Y1S + f1a * 6 + lpLo]       = fmaxf(v0, p0);
                    y1sh[rLo * Y1S + (f1a + 1) * 6 + lpLo] = fmaxf(v1, p1);
                    y1sh[rHi * Y1S + f1a * 6 + lpHi]       = fmaxf(v2, p2);
                    y1sh[rHi * Y1S + (f1a + 1) * 6 + lpHi] = fmaxf(v3, p3);
                }
            }
        }
    }
    __syncthreads();

    // ---- conv2 via 3xTF32 MMA + relu + pool2 (B from global pre-split) ----
    {
        int mt = wrp;
        float acc[8][4];
        #pragma unroll
        for (int nt = 0; nt < 8; nt++)
            #pragma unroll
            for (int s = 0; s < 4; s++) acc[nt][s] = 0.f;

        int rowA = 16 * mt + gr;
        int rA = rowA >> 2, pA = rowA & 3;
        int rB = rA + 2;

        for (int ks = 0; ks < 12; ks++) {
            int k0 = 8 * ks + tg;
            int k1 = k0 + 4;
            int o0 = (k0 / 3) * 6 + (k0 % 3);
            int o1 = (k1 / 3) * 6 + (k1 % 3);
            float a0f = y1sh[rA * Y1S + o0 + pA];
            float a1f = y1sh[rB * Y1S + o0 + pA];
            float a2f = y1sh[rA * Y1S + o1 + pA];
            float a3f = y1sh[rB * Y1S + o1 + pA];
            uint32_t ah0, al0, ah1, al1, ah2, al2, ah3, al3;
            tf32_split(a0f, ah0, al0);
            tf32_split(a1f, ah1, al1);
            tf32_split(a2f, ah2, al2);
            tf32_split(a3f, ah3, al3);

            #pragma unroll
            for (int nt = 0; nt < 8; nt++) {
                int nb = (nt * 8 + gr) * 96;
                float2 w0p = __ldg(&g_w2p[nb + k0]);
                float2 w1p = __ldg(&g_w2p[nb + k1]);
                uint32_t bh0 = __float_as_uint(w0p.x);
                uint32_t bl0 = __float_as_uint(w0p.y);
                uint32_t bh1 = __float_as_uint(w1p.x);
                uint32_t bl1 = __float_as_uint(w1p.y);
                mma3(acc[nt], ah0, al0, ah1, al1, ah2, al2, ah3, al3,
                     bh0, bl0, bh1, bl1);
            }
        }
        __syncthreads();                  // y1/zsh reads done; y2 reuse OK

        #pragma unroll
        for (int nt = 0; nt < 8; nt++) {
            int n0 = nt * 8 + 2 * tg;
            float bias0 = b2sh[n0];
            float bias1 = b2sh[n0 + 1];
            float v0 = fmaxf(acc[nt][0] + bias0, 0.f);
            float v1 = fmaxf(acc[nt][1] + bias1, 0.f);
            float v2 = fmaxf(acc[nt][2] + bias0, 0.f);
            float v3 = fmaxf(acc[nt][3] + bias1, 0.f);
            float p0 = __shfl_xor_sync(0xffffffffu, v0, 4);
            float p1 = __shfl_xor_sync(0xffffffffu, v1, 4);
            float p2 = __shfl_xor_sync(0xffffffffu, v2, 4);
            float p3 = __shfl_xor_sync(0xffffffffu, v3, 4);
            if ((gr & 1) == 0) {
                int pp = (gr & 3) >> 1;
                int ra = 4 * mt + (gr >> 2);
                int rb = ra + 2;
                y2sh[ra * Y2S + n0 * 2 + pp]       = fmaxf(v0, p0);
                y2sh[ra * Y2S + (n0 + 1) * 2 + pp] = fmaxf(v1, p1);
                y2sh[rb * Y2S + n0 * 2 + pp]       = fmaxf(v2, p2);
                y2sh[rb * Y2S + (n0 + 1) * 2 + pp] = fmaxf(v3, p3);
            }
        }
    }
    __syncthreads();                      // y2 complete

    // ---- fc1 via 3xTF32 MMA + relu (B from global fp32, split on the fly) ----
    {
        const float* fb = sm + OFF_F1B;
        int mt  = wrp & 1;
        int nt0 = (wrp >> 1) * 2;
        int rowA = 16 * mt + gr;

        float acc[2][4];
        #pragma unroll
        for (int q = 0; q < 2; q++)
            #pragma unroll
            for (int s = 0; s < 4; s++) acc[q][s] = 0.f;

        for (int ks = 0; ks < 16; ks++) {
            int k0 = 8 * ks + tg;
            int k1 = k0 + 4;
            float a0f = y2sh[rowA * Y2S + k0];
            float a1f = y2sh[(rowA + 8) * Y2S + k0];
            float a2f = y2sh[rowA * Y2S + k1];
            float a3f = y2sh[(rowA + 8) * Y2S + k1];
            uint32_t ah0, al0, ah1, al1, ah2, al2, ah3, al3;
            tf32_split(a0f, ah0, al0);
            tf32_split(a1f, ah1, al1);
            tf32_split(a2f, ah2, al2);
            tf32_split(a3f, ah3, al3);

            #pragma unroll
            for (int q = 0; q < 2; q++) {
                int n = (nt0 + q) * 8 + gr;
                float b0f = __ldg(&f1wg[n * 128 + k0]);
                float b1f = __ldg(&f1wg[n * 128 + k1]);
                uint32_t bh0, bl0, bh1, bl1;
                tf32_split(b0f, bh0, bl0);
                tf32_split(b1f, bh1, bl1);
                mma3(acc[q], ah0, al0, ah1, al1, ah2, al2, ah3, al3,
                     bh0, bl0, bh1, bl1);
            }
        }
        #pragma unroll
        for (int q = 0; q < 2; q++) {
            int n0 = (nt0 + q) * 8 + 2 * tg;
            float ba = fb[n0], bb = fb[n0 + 1];
            hsh[rowA * HS + n0]           = fmaxf(acc[q][0] + ba, 0.f);
            hsh[rowA * HS + n0 + 1]       = fmaxf(acc[q][1] + bb, 0.f);
            hsh[(rowA + 8) * HS + n0]     = fmaxf(acc[q][2] + ba, 0.f);
            hsh[(rowA + 8) * HS + n0 + 1] = fmaxf(acc[q][3] + bb, 0.f);
        }
    }
    __syncthreads();

    // ---- fc2 + transposed output write: out[b,t,o,n] ----
    if (tid < 160) {
        const float* fc2w = sm + OFF_F2W;
        const float* fc2b = sm + OFF_F2B;
        int r = tid & 31, o = tid >> 5;
        float acc = fc2b[o];
        #pragma unroll 8
        for (int j = 0; j < 64; j++)
            acc = fmaf(hsh[r * HS + j], fc2w[o * 64 + j], acc);
        int R  = row0 + r;
        int n  = R % NN;
        int bt = R / NN;
        out[((size_t)bt * 5 + o) * NN + n] = acc;
    }
}

// ---------------------------------------------------------------------------
extern "C" void kernel_launch(void* const* d_in, const int* in_sizes, int n_in,
                              void* d_out, int out_size)
{
    const float* x   = (const float*)d_in[0];
    const float* S   = (const float*)d_in[1];
    const float* w1  = (const float*)d_in[2];
    const float* b1  = (const float*)d_in[3];
    const float* w2  = (const float*)d_in[4];
    const float* b2  = (const float*)d_in[5];
    const float* f1w = (const float*)d_in[6];
    const float* f1b = (const float*)d_in[7];
    const float* f2w = (const float*)d_in[8];
    const float* f2b = (const float*)d_in[9];
    float* out = (float*)d_out;

    split_w2_kernel<<<24, 256>>>(w2);

    for (int k = 1; k <= 15; k++)
        diffuse_step_kernel<<<BT, 128>>>(x, S, k);

    size_t smem = (size_t)SMEM_FLOATS * sizeof(float);
    cudaFuncSetAttribute(head_kernel,
                         cudaFuncAttributeMaxDynamicSharedMemorySize, (int)smem);
    head_kernel<<<(NB * NT * NN) / 32, 256, smem>>>(
        x, w1, b1, w2, b2, f1w, f1b, f2w, f2b, out);
}